// round 16
// baseline (speedup 1.0000x reference)
// R16 = R15 + software-pipelined W loads (prefetch depth 1).
// R15 measured: 66.3us, DRAM 48.6% (binder), issue 20%, L1 35%, regs 72.
// Loads for iter it+1 are issued after packing iter it's words (pack frees
// the 32 pf regs first), hiding ~380cyc DRAM latency under compute.
#include <cuda_runtime.h>
#include <cuda_fp16.h>
#include <cstdint>
#include <cstddef>

#define OUT_F 8192
#define IN_F  8192
#define NCOL  16
#define KS     16                 // K-splits across blockIdx.y
#define KBLK   (IN_F / KS)        // 512 k per block
#define ST     258                // smem words per col (256 + 2 pad): conflict-free
#define TPB    256
#define ROWS_PER_WARP 16
#define ROWS_PER_BLK  128         // 8 warps * 16 rows
#define NGRP   (OUT_F / ROWS_PER_BLK)   // 64 row-groups
#define NIT    (KBLK / 64)        // 8 chunks of 64 k

// --- device scratch (no allocations allowed) ---
__device__ float psum[KS * OUT_F * NCOL];   // K-split partials (8 MiB)
__device__ int   g_cnt[NGRP];               // arrival counters (self-resetting)

// Pack low bytes of 4 sign-extended int32 weights into one word.
__device__ __forceinline__ uint32_t packw(uint4 v) {
    return (v.x & 0xFFu) | ((v.y & 0xFFu) << 8) | ((v.z & 0xFFu) << 16) | (v.w << 24);
}

// int8 -> fp16 exact conversion (magic number). Input already XOR 0x80808080.
__device__ __forceinline__ uint32_t cvt_lo(uint32_t wx) {
    uint32_t p = __byte_perm(wx, 0x64006400u, 0x7150);   // {1024+b0, 1024+b1}
    uint32_t r;
    asm("add.rn.f16x2 %0, %1, %2;" : "=r"(r) : "r"(p), "r"(0xE480E480u)); // -1152
    return r;
}
__device__ __forceinline__ uint32_t cvt_hi(uint32_t wx) {
    uint32_t p = __byte_perm(wx, 0x64006400u, 0x7352);   // {1024+b2, 1024+b3}
    uint32_t r;
    asm("add.rn.f16x2 %0, %1, %2;" : "=r"(r) : "r"(p), "r"(0xE480E480u));
    return r;
}

// m16n8k8 fp16 MMA, fp32 accum. A row-major {a0: rows 0-7, a1: rows 8-15}.
__device__ __forceinline__ void mma1688(float* c, uint32_t a0, uint32_t a1, uint32_t b0) {
    asm volatile(
        "mma.sync.aligned.m16n8k8.row.col.f32.f16.f16.f32 "
        "{%0,%1,%2,%3}, {%4,%5}, {%6}, {%0,%1,%2,%3};"
        : "+f"(c[0]), "+f"(c[1]), "+f"(c[2]), "+f"(c[3])
        : "r"(a0), "r"(a1), "r"(b0));
}

// ------------------------------------------------------------------
// Fused kernel: split x slice into fp16 hi/lo in SMEM (k-words stored
// with q/cq fields swapped to match the coalesced A-load k-map), fp16
// MMA GEMM with prefetched W loads, K-split partials, last-block tail
// reduction into out.
//   Lane (r0,cq), load instr q: W int offset = it*64 + q*16 + cq*4
//   -> per row 4 lanes read 64B contiguous (full sector utilization).
//   Lane k-quad (group g) = it*64 + g*16 + cq*4 + {0..3}; stored at
//   physical p = 8cq+2g+b, so the consumer reads kw = it*32+8cq+2g
//   (bank-conflict-free, measured R13/R15).
// ------------------------------------------------------------------
__global__ __launch_bounds__(TPB, 3)
void gemm_kernel(const int* __restrict__ W, const float* __restrict__ x,
                 const float* __restrict__ scal, float4* __restrict__ out4) {
    __shared__ uint32_t s_x[32 * ST];      // 33 KB
    __shared__ int s_last;

    const int tid   = threadIdx.x;
    const int ky    = blockIdx.y;
    const int bx    = blockIdx.x;
    const int kbase = ky * KBLK;

    // ---- stage x slice as fp16 hi/lo pairs, with permuted word placement ----
    for (int slot = tid; slot < (KBLK / 2) * NCOL; slot += TPB) {
        const int k2 = slot >> 4;          // 0..255: logical word (pair of k)
        const int c  = slot & 15;
        float v0 = x[(kbase + 2 * k2)     * NCOL + c];
        float v1 = x[(kbase + 2 * k2 + 1) * NCOL + c];
        __half h0 = __float2half_rn(v0);
        __half h1 = __float2half_rn(v1);
        __half l0 = __float2half_rn(v0 - __half2float(h0));
        __half l1 = __float2half_rn(v1 - __half2float(h1));
        // field swap within each 32-word chunk: l = 8q+2cq+b -> p = 8cq+2q+b
        const int l    = k2 & 31;
        const int p    = ((l & 6) << 2) | ((l >> 2) & 6) | (l & 1);
        const int phys = (k2 & ~31) | p;
        s_x[c * ST + phys] = (uint32_t)__half_as_ushort(h0)
                           | ((uint32_t)__half_as_ushort(h1) << 16);
        s_x[(c + 16) * ST + phys] = (uint32_t)__half_as_ushort(l0)
                                  | ((uint32_t)__half_as_ushort(l1) << 16);
    }
    __syncthreads();

    // ---- main loop: warp = 16 rows x 32 B-cols, chunks of 64 k ----
    const int lane = tid & 31;
    const int wid  = tid >> 5;
    const int r0   = lane >> 2;            // 0..7: A-row group / B-col in tile
    const int cq   = lane & 3;             // 0..3: k sub-offset (x4 ints)
    const int row0 = bx * ROWS_PER_BLK + wid * ROWS_PER_WARP;

    const int* wp = W + (size_t)(row0 + r0) * IN_F + kbase + cq * 4;

    float acc[4][4];                       // [t: n8 tile][c-frag]
#pragma unroll
    for (int t = 0; t < 4; t++)
#pragma unroll
        for (int i = 0; i < 4; i++) acc[t][i] = 0.f;

    // prefetch iter 0
    uint4 pf[2][4];                        // [row r0 / r0+8][q: 16-int step]
#pragma unroll
    for (int rs = 0; rs < 2; rs++)
#pragma unroll
        for (int q = 0; q < 4; q++)
            pf[rs][q] = __ldcs((const uint4*)(wp + (size_t)rs * 8 * IN_F + 16 * q));

    for (int it = 0; it < NIT; it++) {
        // pack + bias current iter (frees the 32 pf registers)...
        uint32_t wpk[2][4];
#pragma unroll
        for (int rs = 0; rs < 2; rs++)
#pragma unroll
            for (int q = 0; q < 4; q++)
                wpk[rs][q] = packw(pf[rs][q]) ^ 0x80808080u;

        // ...then issue next iter's loads so they overlap this iter's MMAs
        if (it + 1 < NIT) {
            const int knext = (it + 1) * 64;
#pragma unroll
            for (int rs = 0; rs < 2; rs++)
#pragma unroll
                for (int q = 0; q < 4; q++)
                    pf[rs][q] = __ldcs((const uint4*)(wp + (size_t)rs * 8 * IN_F + knext + 16 * q));
        }

#pragma unroll
        for (int g = 0; g < 4; g++) {
            const int kw = it * 32 + 8 * cq + 2 * g;   // physical half2 word

            uint2 bb[4];
#pragma unroll
            for (int t = 0; t < 4; t++)
                bb[t] = *(const uint2*)&s_x[(8 * t + r0) * ST + kw];

            uint32_t l0 = cvt_lo(wpk[0][g]), h0 = cvt_hi(wpk[0][g]);   // row r0
            uint32_t l1 = cvt_lo(wpk[1][g]), h1 = cvt_hi(wpk[1][g]);   // row r0+8
#pragma unroll
            for (int t = 0; t < 4; t++) {
                mma1688(acc[t], l0, l1, bb[t].x);   // k, k+1
                mma1688(acc[t], h0, h1, bb[t].y);   // k+2, k+3
            }
        }
    }

    // ---- epilogue: combine hi (t) + lo (t+2), scale, K-split partials ----
    const float s = scal[0];
#pragma unroll
    for (int i = 0; i < 2; i++) {          // c-frag row: r0 + 8i
        const int row = row0 + r0 + 8 * i;
#pragma unroll
        for (int t = 0; t < 2; t++) {      // cols 8t + 2cq
            float2 v;
            v.x = s * (acc[t][2 * i]     + acc[t + 2][2 * i]);
            v.y = s * (acc[t][2 * i + 1] + acc[t + 2][2 * i + 1]);
            *(float2*)&psum[((size_t)ky * OUT_F + row) * NCOL + 8 * t + 2 * cq] = v;
        }
    }

    // ---- tail: last of the KS blocks in this row-group reduces to out ----
    __threadfence();                 // publish psum writes
    if (tid == 0) {
        int old = atomicAdd(&g_cnt[bx], 1);
        int last = (old == KS - 1);
        if (last) g_cnt[bx] = 0;     // self-reset for next graph replay
        s_last = last;
    }
    __syncthreads();
    if (!s_last) return;
    __threadfence();                 // acquire other blocks' psum writes

    const float4* psum4 = (const float4*)psum;
    const int nf4 = ROWS_PER_BLK * NCOL / 4;            // 512
    for (int i4 = tid; i4 < nf4; i4 += TPB) {
        const int base = bx * nf4 + i4;                  // float4 index in slice 0
        float4 a = psum4[base];
#pragma unroll
        for (int j = 1; j < KS; j++) {
            float4 b = psum4[(size_t)j * (OUT_F * NCOL / 4) + base];
            a.x += b.x; a.y += b.y; a.z += b.z; a.w += b.w;
        }
        out4[base] = a;
    }
}

extern "C" void kernel_launch(void* const* d_in, const int* in_sizes, int n_in,
                              void* d_out, int out_size) {
    // Bind inputs by size (element counts; byte counts also accepted)
    const float* x    = nullptr;
    const int*   W    = nullptr;   // int8 weights delivered as int32 by harness
    const float* scal = nullptr;
    for (int i = 0; i < n_in; i++) {
        long sz = in_sizes[i];
        if (sz == (long)IN_F * NCOL || sz == (long)IN_F * NCOL * 4)
            x = (const float*)d_in[i];
        else if (sz == (long)OUT_F * IN_F || sz == (long)OUT_F * IN_F * 4)
            W = (const int*)d_in[i];
        else if (sz == 1 || sz == 4)
            scal = (const float*)d_in[i];
    }
    if (!x)    x    = (const float*)d_in[0];
    if (!W)    W    = (const int*)d_in[1];
    if (!scal) scal = (const float*)d_in[2];
    float4* out4 = (float4*)d_out;

    dim3 grid(NGRP, KS);   // (64, 16)
    gemm_kernel<<<grid, TPB>>>(W, x, scal, out4);
}

// round 17
// speedup vs baseline: 1.2242x; 1.2242x over previous
// R17 = R15 core (measured best, 66.3us) with KS 16 -> 32 to cut wave-
// quantization tail (1024 blocks / 444 concurrent = 2.31 waves, ~23% idle
// -> 2048 blocks = 4.61 waves, ~8% idle). Manual prefetch retired after
// two regressions (R8 spills, R16 slower at same occ) — ptxas schedules
// the R15 load placement better than hand pipelining.
#include <cuda_runtime.h>
#include <cuda_fp16.h>
#include <cstdint>
#include <cstddef>

#define OUT_F 8192
#define IN_F  8192
#define NCOL  16
#define KS     32                 // K-splits across blockIdx.y
#define KBLK   (IN_F / KS)        // 256 k per block
#define ST     130                // smem words per col (128 + 2 pad): ST%32==2, conflict-free
#define TPB    256
#define ROWS_PER_WARP 16
#define ROWS_PER_BLK  128         // 8 warps * 16 rows
#define NGRP   (OUT_F / ROWS_PER_BLK)   // 64 row-groups
#define NIT    (KBLK / 64)        // 4 chunks of 64 k

// --- device scratch (no allocations allowed) ---
__device__ float psum[KS * OUT_F * NCOL];   // K-split partials (16 MiB)
__device__ int   g_cnt[NGRP];               // arrival counters (self-resetting)

// Pack low bytes of 4 sign-extended int32 weights into one word.
__device__ __forceinline__ uint32_t packw(uint4 v) {
    return (v.x & 0xFFu) | ((v.y & 0xFFu) << 8) | ((v.z & 0xFFu) << 16) | (v.w << 24);
}

// int8 -> fp16 exact conversion (magic number). Input already XOR 0x80808080.
__device__ __forceinline__ uint32_t cvt_lo(uint32_t wx) {
    uint32_t p = __byte_perm(wx, 0x64006400u, 0x7150);   // {1024+b0, 1024+b1}
    uint32_t r;
    asm("add.rn.f16x2 %0, %1, %2;" : "=r"(r) : "r"(p), "r"(0xE480E480u)); // -1152
    return r;
}
__device__ __forceinline__ uint32_t cvt_hi(uint32_t wx) {
    uint32_t p = __byte_perm(wx, 0x64006400u, 0x7352);   // {1024+b2, 1024+b3}
    uint32_t r;
    asm("add.rn.f16x2 %0, %1, %2;" : "=r"(r) : "r"(p), "r"(0xE480E480u));
    return r;
}

// m16n8k8 fp16 MMA, fp32 accum. A row-major {a0: rows 0-7, a1: rows 8-15}.
__device__ __forceinline__ void mma1688(float* c, uint32_t a0, uint32_t a1, uint32_t b0) {
    asm volatile(
        "mma.sync.aligned.m16n8k8.row.col.f32.f16.f16.f32 "
        "{%0,%1,%2,%3}, {%4,%5}, {%6}, {%0,%1,%2,%3};"
        : "+f"(c[0]), "+f"(c[1]), "+f"(c[2]), "+f"(c[3])
        : "r"(a0), "r"(a1), "r"(b0));
}

// ------------------------------------------------------------------
// Fused kernel: split x slice into fp16 hi/lo in SMEM (k-words stored
// with q/cq fields swapped to match the coalesced A-load k-map), fp16
// MMA GEMM, K-split partials, last-block tail reduction into out.
//   Lane (r0,cq), load instr q: W int offset = it*64 + q*16 + cq*4
//   -> per row 4 lanes read 64B contiguous (full sector utilization).
//   Lane k-quad (group g) = it*64 + g*16 + cq*4 + {0..3}; stored at
//   physical p = 8cq+2g+b, so the consumer reads kw = it*32+8cq+2g
//   (bank-conflict-free: bank = 2*r0 + 8*cq + ... distinct per phase).
// ------------------------------------------------------------------
__global__ __launch_bounds__(TPB, 3)
void gemm_kernel(const int* __restrict__ W, const float* __restrict__ x,
                 const float* __restrict__ scal, float4* __restrict__ out4) {
    __shared__ uint32_t s_x[32 * ST];      // 16.7 KB
    __shared__ int s_last;

    const int tid   = threadIdx.x;
    const int ky    = blockIdx.y;
    const int bx    = blockIdx.x;
    const int kbase = ky * KBLK;

    // ---- stage x slice as fp16 hi/lo pairs, with permuted word placement ----
    for (int slot = tid; slot < (KBLK / 2) * NCOL; slot += TPB) {
        const int k2 = slot >> 4;          // 0..127: logical word (pair of k)
        const int c  = slot & 15;
        float v0 = x[(kbase + 2 * k2)     * NCOL + c];
        float v1 = x[(kbase + 2 * k2 + 1) * NCOL + c];
        __half h0 = __float2half_rn(v0);
        __half h1 = __float2half_rn(v1);
        __half l0 = __float2half_rn(v0 - __half2float(h0));
        __half l1 = __float2half_rn(v1 - __half2float(h1));
        // field swap within each 32-word chunk: l = 8q+2cq+b -> p = 8cq+2q+b
        const int l    = k2 & 31;
        const int p    = ((l & 6) << 2) | ((l >> 2) & 6) | (l & 1);
        const int phys = (k2 & ~31) | p;
        s_x[c * ST + phys] = (uint32_t)__half_as_ushort(h0)
                           | ((uint32_t)__half_as_ushort(h1) << 16);
        s_x[(c + 16) * ST + phys] = (uint32_t)__half_as_ushort(l0)
                                  | ((uint32_t)__half_as_ushort(l1) << 16);
    }
    __syncthreads();

    // ---- main loop: warp = 16 rows x 32 B-cols, chunks of 64 k ----
    const int lane = tid & 31;
    const int wid  = tid >> 5;
    const int r0   = lane >> 2;            // 0..7: A-row group / B-col in tile
    const int cq   = lane & 3;             // 0..3: k sub-offset (x4 ints)
    const int row0 = bx * ROWS_PER_BLK + wid * ROWS_PER_WARP;

    const int* wp = W + (size_t)(row0 + r0) * IN_F + kbase + cq * 4;

    float acc[4][4];                       // [t: n8 tile][c-frag]
#pragma unroll
    for (int t = 0; t < 4; t++)
#pragma unroll
        for (int i = 0; i < 4; i++) acc[t][i] = 0.f;

    for (int it = 0; it < NIT; it++) {
        const int k0 = it * 64;            // chunk base (lane offset in wp)

        uint4 wq[2][4];                    // [row r0 / r0+8][q: 16-int step]
#pragma unroll
        for (int rs = 0; rs < 2; rs++)
#pragma unroll
            for (int q = 0; q < 4; q++)
                wq[rs][q] = __ldcs((const uint4*)(wp + (size_t)rs * 8 * IN_F + k0 + 16 * q));

#pragma unroll
        for (int g = 0; g < 4; g++) {
            const int kw = it * 32 + 8 * cq + 2 * g;   // physical half2 word

            uint2 bb[4];
#pragma unroll
            for (int t = 0; t < 4; t++)
                bb[t] = *(const uint2*)&s_x[(8 * t + r0) * ST + kw];

            uint32_t w0 = packw(wq[0][g]) ^ 0x80808080u;   // row r0,   k-quad g
            uint32_t w1 = packw(wq[1][g]) ^ 0x80808080u;   // row r0+8, k-quad g
            uint32_t l0 = cvt_lo(w0), h0 = cvt_hi(w0);
            uint32_t l1 = cvt_lo(w1), h1 = cvt_hi(w1);
#pragma unroll
            for (int t = 0; t < 4; t++) {
                mma1688(acc[t], l0, l1, bb[t].x);   // k, k+1
                mma1688(acc[t], h0, h1, bb[t].y);   // k+2, k+3
            }
        }
    }

    // ---- epilogue: combine hi (t) + lo (t+2), scale, K-split partials ----
    const float s = scal[0];
#pragma unroll
    for (int i = 0; i < 2; i++) {          // c-frag row: r0 + 8i
        const int row = row0 + r0 + 8 * i;
#pragma unroll
        for (int t = 0; t < 2; t++) {      // cols 8t + 2cq
            float2 v;
            v.x = s * (acc[t][2 * i]     + acc[t + 2][2 * i]);
            v.y = s * (acc[t][2 * i + 1] + acc[t + 2][2 * i + 1]);
            *(float2*)&psum[((size_t)ky * OUT_F + row) * NCOL + 8 * t + 2 * cq] = v;
        }
    }

    // ---- tail: last of the KS blocks in this row-group reduces to out ----
    __threadfence();                 // publish psum writes
    if (tid == 0) {
        int old = atomicAdd(&g_cnt[bx], 1);
        int last = (old == KS - 1);
        if (last) g_cnt[bx] = 0;     // self-reset for next graph replay
        s_last = last;
    }
    __syncthreads();
    if (!s_last) return;
    __threadfence();                 // acquire other blocks' psum writes

    const float4* psum4 = (const float4*)psum;
    const int nf4 = ROWS_PER_BLK * NCOL / 4;            // 512
    for (int i4 = tid; i4 < nf4; i4 += TPB) {
        const int base = bx * nf4 + i4;                  // float4 index in slice 0
        float4 a = psum4[base];
#pragma unroll
        for (int j = 1; j < KS; j++) {
            float4 b = psum4[(size_t)j * (OUT_F * NCOL / 4) + base];
            a.x += b.x; a.y += b.y; a.z += b.z; a.w += b.w;
        }
        out4[base] = a;
    }
}

extern "C" void kernel_launch(void* const* d_in, const int* in_sizes, int n_in,
                              void* d_out, int out_size) {
    // Bind inputs by size (element counts; byte counts also accepted)
    const float* x    = nullptr;
    const int*   W    = nullptr;   // int8 weights delivered as int32 by harness
    const float* scal = nullptr;
    for (int i = 0; i < n_in; i++) {
        long sz = in_sizes[i];
        if (sz == (long)IN_F * NCOL || sz == (long)IN_F * NCOL * 4)
            x = (const float*)d_in[i];
        else if (sz == (long)OUT_F * IN_F || sz == (long)OUT_F * IN_F * 4)
            W = (const int*)d_in[i];
        else if (sz == 1 || sz == 4)
            scal = (const float*)d_in[i];
    }
    if (!x)    x    = (const float*)d_in[0];
    if (!W)    W    = (const int*)d_in[1];
    if (!scal) scal = (const float*)d_in[2];
    float4* out4 = (float4*)d_out;

    dim3 grid(NGRP, KS);   // (64, 32)
    gemm_kernel<<<grid, TPB>>>(W, x, scal, out4);
}